// round 1
// baseline (speedup 1.0000x reference)
#include <cuda_runtime.h>
#include <cstdint>

// STFT via per-frame 2048-point radix-2 FFT in shared memory.
// Reference: out[b,t,f] = sum_n x_pad[b, t*512 + n] * hann[n] * exp(-2*pi*i*f*n/2048)
// pad_l = pad_r = 768 (zeros). Output: real[64*63*1024] then imag[64*63*1024].

#define WINDOW   2048
#define STRIDE   512
#define FREQ     1024
#define FRAMES   63
#define SIG_LEN  32256
#define BATCH    64
#define PAD_L    768
#define NTHREADS 256

__global__ __launch_bounds__(NTHREADS) void stft_fft_kernel(
    const float* __restrict__ x,   // [BATCH, SIG_LEN]
    float* __restrict__ out)       // [2, BATCH*FRAMES, FREQ]
{
    __shared__ float sr[WINDOW];
    __shared__ float si[WINDOW];
    __shared__ float twr[FREQ];
    __shared__ float twi[FREQ];

    const int tid = threadIdx.x;
    const int m   = blockIdx.x;          // 0 .. 4031
    const int b   = m / FRAMES;
    const int t   = m - b * FRAMES;

    const float* xb  = x + (size_t)b * SIG_LEN;
    const int base   = t * STRIDE - PAD_L;

    const float TWO_PI_OVER_N = 6.283185307179586f / (float)WINDOW;

    // Twiddle table: tw[j] = exp(-2*pi*i*j/2048), j in [0,1024)
    #pragma unroll
    for (int j = tid; j < FREQ; j += NTHREADS) {
        float ang = -TWO_PI_OVER_N * (float)j;
        float s, c;
        __sincosf(ang, &s, &c);
        twr[j] = c;
        twi[j] = s;
    }

    // Load + zero-pad + Hann window + bit-reversed placement (DIT input)
    #pragma unroll
    for (int j = tid; j < WINDOW; j += NTHREADS) {
        int sidx = base + j;
        float v = (sidx >= 0 && sidx < SIG_LEN) ? xb[sidx] : 0.0f;
        float w = 0.5f - 0.5f * __cosf(TWO_PI_OVER_N * (float)j);
        int r = __brev((unsigned)j) >> 21;   // 11-bit reversal
        sr[r] = v * w;
        si[r] = 0.0f;
    }
    __syncthreads();

    // 11 radix-2 DIT stages (in-place, natural-order output)
    #pragma unroll
    for (int s = 1; s <= 11; s++) {
        const int half = 1 << (s - 1);
        const int step = FREQ >> (s - 1);   // twiddle stride: 1024/half
        #pragma unroll
        for (int i = tid; i < FREQ; i += NTHREADS) {
            int j = i & (half - 1);
            int k = ((i >> (s - 1)) << s) + j;
            float wr = twr[j * step];
            float wi = twi[j * step];
            float ar = sr[k],        ai = si[k];
            float br = sr[k + half], bi = si[k + half];
            float tr = br * wr - bi * wi;
            float ti = br * wi + bi * wr;
            sr[k]        = ar + tr;
            si[k]        = ai + ti;
            sr[k + half] = ar - tr;
            si[k + half] = ai - ti;
        }
        __syncthreads();
    }

    // Write first 1024 bins: real block then imag block
    float* outr = out + (size_t)m * FREQ;
    float* outi = out + (size_t)BATCH * FRAMES * FREQ + (size_t)m * FREQ;
    #pragma unroll
    for (int f = tid; f < FREQ; f += NTHREADS) {
        outr[f] = sr[f];
        outi[f] = si[f];
    }
}

extern "C" void kernel_launch(void* const* d_in, const int* in_sizes, int n_in,
                              void* d_out, int out_size)
{
    const float* x = (const float*)d_in[0];   // input_signal [64, 32256, 1]
    // d_in[1] (real_kernel) and d_in[2] (imag_kernel) are unused:
    // twiddles/window are regenerated exactly on device.
    float* out = (float*)d_out;

    stft_fft_kernel<<<BATCH * FRAMES, NTHREADS>>>(x, out);
}

// round 2
// speedup vs baseline: 5.9986x; 5.9986x over previous
#include <cuda_runtime.h>
#include <cstdint>

// STFT via 2048-pt complex FFT, two real frames per FFT (A=re, B=im).
// DIT, bit-reversed input, 4 register passes (radix-8 x3 + radix-4),
// padded smem layout phys(k)=k+(k>>3) for bank-conflict avoidance.
// Twiddles computed on the fly: one __sincosf per pass per thread.

#define WINDOW   2048
#define STRIDE   512
#define FREQ     1024
#define FRAMES   63
#define SIG_LEN  32256
#define BATCH    64
#define PAD_L    768
#define NT       256
#define NPAIRS   ((BATCH * FRAMES) / 2)   // 2016

__device__ __forceinline__ float2 cmul(float2 a, float2 b) {
    return make_float2(fmaf(a.x, b.x, -a.y * b.y), fmaf(a.x, b.y, a.y * b.x));
}
__device__ __forceinline__ float2 cnegi(float2 a) {   // a * (-i)
    return make_float2(a.y, -a.x);
}
__device__ __forceinline__ int phys(int k) { return k + (k >> 3); }

__device__ __forceinline__ void bfly(float2& lo, float2& hi, float2 tw) {
    float2 u = cmul(hi, tw);
    hi = make_float2(lo.x - u.x, lo.y - u.y);
    lo = make_float2(lo.x + u.x, lo.y + u.y);
}
__device__ __forceinline__ void bfly1(float2& lo, float2& hi) {  // tw = 1
    float2 u = hi;
    hi = make_float2(lo.x - u.x, lo.y - u.y);
    lo = make_float2(lo.x + u.x, lo.y + u.y);
}
__device__ __forceinline__ void bflyni(float2& lo, float2& hi) { // tw = -i
    float2 u = make_float2(hi.y, -hi.x);
    hi = make_float2(lo.x - u.x, lo.y - u.y);
    lo = make_float2(lo.x + u.x, lo.y + u.y);
}

// Generic radix-8 DIT pass: stages use twiddles T3^4, T3^2 (*1,-i), T3 (*1,C8,-i,-iC8)
__device__ __forceinline__ void pass_radix8(float2* E, float2 T3) {
    const float R = 0.70710678118654752440f;
    float2 T2 = cmul(T3, T3);
    float2 T1 = cmul(T2, T2);
    // stage A (bit b0): pairs (0,1)(2,3)(4,5)(6,7), tw = T1
    bfly(E[0], E[1], T1); bfly(E[2], E[3], T1);
    bfly(E[4], E[5], T1); bfly(E[6], E[7], T1);
    // stage B (bit b1): tw(b0=0)=T2, tw(b0=1)=-i*T2
    float2 T2n = cnegi(T2);
    bfly(E[0], E[2], T2);  bfly(E[1], E[3], T2n);
    bfly(E[4], E[6], T2);  bfly(E[5], E[7], T2n);
    // stage C (bit b2): tw = T3 * {1, C8, -i, -i*C8},  C8 = (1-i)/sqrt2
    float2 C8  = make_float2(R, -R);
    float2 T3b = cmul(T3, C8);
    float2 T3c = cnegi(T3);
    float2 T3d = cnegi(T3b);
    bfly(E[0], E[4], T3);
    bfly(E[1], E[5], T3b);
    bfly(E[2], E[6], T3c);
    bfly(E[3], E[7], T3d);
}

// Radix-4 DIT pass (stages 10,11): tw stage10 = T^2; stage11 = T, -i*T
__device__ __forceinline__ void pass_radix4(float2* G, float2 T) {
    float2 T2 = cmul(T, T);
    bfly(G[0], G[1], T2);
    bfly(G[2], G[3], T2);
    bfly(G[0], G[2], T);
    float2 Tn = cnegi(T);
    bfly(G[1], G[3], Tn);
}

__global__ __launch_bounds__(NT) void stft_kernel(const float* __restrict__ x,
                                                  float* __restrict__ out)
{
    __shared__ float2 zz[2304];   // 2048 + 256 padding

    const int t = threadIdx.x;
    const int pr = blockIdx.x;
    const int m0 = 2 * pr, m1 = m0 + 1;
    const int ba = m0 / FRAMES, fa = m0 - ba * FRAMES;
    const int bb = m1 / FRAMES, fb = m1 - bb * FRAMES;
    const float* xA = x + ba * SIG_LEN;
    const float* xB = x + bb * SIG_LEN;
    const int baseA = fa * STRIDE - PAD_L;
    const int baseB = fb * STRIDE - PAD_L;

    // ---- stage windowed signal: zz[phys(n)] = hann(n) * (xA(n) + i*xB(n))
    {
        const float R = 0.70710678118654752440f;
        float sn, cs;
        __sincosf(3.06796157577128245e-3f * (float)t, &sn, &cs); // 2*pi*t/2048
        #pragma unroll
        for (int i = 0; i < 8; i++) {
            int n = t + 256 * i;
            float w = 0.5f - 0.5f * cs;
            int ia = baseA + n, ib = baseB + n;
            float va = (ia >= 0 && ia < SIG_LEN) ? xA[ia] : 0.0f;
            float vb = (ib >= 0 && ib < SIG_LEN) ? xB[ib] : 0.0f;
            zz[phys(n)] = make_float2(w * va, w * vb);
            float c2 = (cs - sn) * R;   // rotate by +pi/4 (step of 256 samples)
            float s2 = (sn + cs) * R;
            cs = c2; sn = s2;
        }
    }
    __syncthreads();

    float2 E[8];

    // ---- pass 0: elements k = 8t+j, input at bit-reversed position
    {
        const int rev3[8] = {0, 4, 2, 6, 1, 5, 3, 7};
        int rt = (int)(__brev((unsigned)t) >> 24);   // rev8(t)
        #pragma unroll
        for (int j = 0; j < 8; j++)
            E[j] = zz[phys((rev3[j] << 8) + rt)];
        __syncthreads();   // in-place: all reads done before writes

        // radix-8 with T3 = 1 (trivial twiddles)
        const float R = 0.70710678118654752440f;
        bfly1(E[0], E[1]); bfly1(E[2], E[3]); bfly1(E[4], E[5]); bfly1(E[6], E[7]);
        bfly1(E[0], E[2]); bflyni(E[1], E[3]);
        bfly1(E[4], E[6]); bflyni(E[5], E[7]);
        bfly1(E[0], E[4]);
        { // tw = C8 = (1-i)/sqrt2
            float2 h = E[5];
            float2 u = make_float2(R * (h.x + h.y), R * (h.y - h.x));
            E[5] = make_float2(E[1].x - u.x, E[1].y - u.y);
            E[1] = make_float2(E[1].x + u.x, E[1].y + u.y);
        }
        bflyni(E[2], E[6]);
        { // tw = -i*C8 = (-1-i)/sqrt2
            float2 h = E[7];
            float2 u = make_float2(R * (h.y - h.x), -R * (h.x + h.y));
            E[7] = make_float2(E[3].x - u.x, E[3].y - u.y);
            E[3] = make_float2(E[3].x + u.x, E[3].y + u.y);
        }
        int wb = 9 * t;   // phys(8t+j) = 9t+j, contiguous
        #pragma unroll
        for (int j = 0; j < 8; j++) zz[wb + j] = E[j];
    }
    __syncthreads();

    // ---- pass 1: h=8, base = (t&7) + ((t>>3)<<6), T3 = W^(32*(t&7))
    {
        int bl = t & 7;
        int base = bl + ((t >> 3) << 6);
        #pragma unroll
        for (int j = 0; j < 8; j++) E[j] = zz[phys(base + 8 * j)];
        float2 T3; __sincosf(-9.81747704246810387e-2f * (float)bl, &T3.y, &T3.x); // -pi/32 * bl
        pass_radix8(E, T3);
        #pragma unroll
        for (int j = 0; j < 8; j++) zz[phys(base + 8 * j)] = E[j];
    }
    __syncthreads();

    // ---- pass 2: h=64, base = (t&63) + ((t>>6)<<9), T3 = W^(4*(t&63))
    {
        int bl = t & 63;
        int base = bl + ((t >> 6) << 9);
        #pragma unroll
        for (int j = 0; j < 8; j++) E[j] = zz[phys(base + 64 * j)];
        float2 T3; __sincosf(-1.22718463030851298e-2f * (float)bl, &T3.y, &T3.x); // -pi/256 * bl
        pass_radix8(E, T3);
        #pragma unroll
        for (int j = 0; j < 8; j++) zz[phys(base + 64 * j)] = E[j];
    }
    __syncthreads();

    // ---- pass 3: two radix-4 groups, c3 = t and t+256, T = W^c3
    {
        const float R = 0.70710678118654752440f;
        float2 G[4], H[4];
        #pragma unroll
        for (int j = 0; j < 4; j++) G[j] = zz[phys(t + 512 * j)];
        #pragma unroll
        for (int j = 0; j < 4; j++) H[j] = zz[phys(t + 256 + 512 * j)];
        float2 T; __sincosf(-3.06796157577128245e-3f * (float)t, &T.y, &T.x); // -pi/1024 * t
        float2 C8 = make_float2(R, -R);
        float2 Tb = cmul(T, C8);   // W^(t+256)
        pass_radix4(G, T);
        pass_radix4(H, Tb);
        #pragma unroll
        for (int j = 0; j < 4; j++) zz[phys(t + 512 * j)] = G[j];
        #pragma unroll
        for (int j = 0; j < 4; j++) zz[phys(t + 256 + 512 * j)] = H[j];
    }
    __syncthreads();

    // ---- epilogue: split Z into the two real-frame spectra, store bins 0..1023
    {
        float* outRA = out + (size_t)m0 * FREQ;
        float* outRB = out + (size_t)m1 * FREQ;
        float* outIA = out + (size_t)(BATCH * FRAMES) * FREQ + (size_t)m0 * FREQ;
        float* outIB = out + (size_t)(BATCH * FRAMES) * FREQ + (size_t)m1 * FREQ;
        #pragma unroll
        for (int i = 0; i < 4; i++) {
            int f = t + 256 * i;
            int g = (WINDOW - f) & (WINDOW - 1);
            float2 Zf = zz[phys(f)];
            float2 Zg = zz[phys(g)];
            outRA[f] = 0.5f * (Zf.x + Zg.x);
            outIA[f] = 0.5f * (Zf.y - Zg.y);
            outRB[f] = 0.5f * (Zf.y + Zg.y);
            outIB[f] = 0.5f * (Zg.x - Zf.x);
        }
    }
}

extern "C" void kernel_launch(void* const* d_in, const int* in_sizes, int n_in,
                              void* d_out, int out_size)
{
    const float* x = (const float*)d_in[0];   // input_signal [64, 32256, 1]
    float* out = (float*)d_out;               // [2, 4032, 1024]
    stft_kernel<<<NPAIRS, NT>>>(x, out);
}

// round 3
// speedup vs baseline: 6.5867x; 1.0980x over previous
#include <cuda_runtime.h>
#include <cstdint>

// STFT via 2048-pt complex FFT, two real frames per FFT (A=re, B=im).
// DIT radix 8-8-8-4, padded smem phys(k)=k+(k>>3), double-buffered,
// epilogue (real/imag split) fused into the last pass via the
// c3 in {t, 512-t} group pairing. 4 syncthreads total.

#define WINDOW   2048
#define STRIDE   512
#define FREQ     1024
#define FRAMES   63
#define SIG_LEN  32256
#define BATCH    64
#define PAD_L    768
#define NT       256
#define NPAIRS   ((BATCH * FRAMES) / 2)   // 2016

__device__ __forceinline__ float2 cmul(float2 a, float2 b) {
    return make_float2(fmaf(a.x, b.x, -a.y * b.y), fmaf(a.x, b.y, a.y * b.x));
}
__device__ __forceinline__ float2 cnegi(float2 a) {   // a * (-i)
    return make_float2(a.y, -a.x);
}
__device__ __forceinline__ int phys(int k) { return k + (k >> 3); }

__device__ __forceinline__ void bfly(float2& lo, float2& hi, float2 tw) {
    float2 u = cmul(hi, tw);
    hi = make_float2(lo.x - u.x, lo.y - u.y);
    lo = make_float2(lo.x + u.x, lo.y + u.y);
}
__device__ __forceinline__ void bfly1(float2& lo, float2& hi) {
    float2 u = hi;
    hi = make_float2(lo.x - u.x, lo.y - u.y);
    lo = make_float2(lo.x + u.x, lo.y + u.y);
}
__device__ __forceinline__ void bflyni(float2& lo, float2& hi) { // tw = -i
    float2 u = make_float2(hi.y, -hi.x);
    hi = make_float2(lo.x - u.x, lo.y - u.y);
    lo = make_float2(lo.x + u.x, lo.y + u.y);
}

__device__ __forceinline__ void pass_radix8(float2* E, float2 T3) {
    const float R = 0.70710678118654752440f;
    float2 T2 = cmul(T3, T3);
    float2 T1 = cmul(T2, T2);
    bfly(E[0], E[1], T1); bfly(E[2], E[3], T1);
    bfly(E[4], E[5], T1); bfly(E[6], E[7], T1);
    float2 T2n = cnegi(T2);
    bfly(E[0], E[2], T2);  bfly(E[1], E[3], T2n);
    bfly(E[4], E[6], T2);  bfly(E[5], E[7], T2n);
    float2 C8  = make_float2(R, -R);
    float2 T3b = cmul(T3, C8);
    float2 T3c = cnegi(T3);
    float2 T3d = cnegi(T3b);
    bfly(E[0], E[4], T3);
    bfly(E[1], E[5], T3b);
    bfly(E[2], E[6], T3c);
    bfly(E[3], E[7], T3d);
}

__device__ __forceinline__ void pass_radix4(float2* G, float2 T) {
    float2 T2 = cmul(T, T);
    bfly(G[0], G[1], T2);
    bfly(G[2], G[3], T2);
    bfly(G[0], G[2], T);
    float2 Tn = cnegi(T);
    bfly(G[1], G[3], Tn);
}

// Guarded 16B load: zeros outside [0, SIG_LEN). g0 is 4-aligned.
__device__ __forceinline__ float4 load4(const float* __restrict__ xb, int g0) {
    if ((unsigned)g0 <= (unsigned)(SIG_LEN - 4)) {
        return *(const float4*)(xb + g0);
    }
    float4 v;
    float* p = (float*)&v;
    #pragma unroll
    for (int u = 0; u < 4; u++)
        p[u] = ((unsigned)(g0 + u) < (unsigned)SIG_LEN) ? xb[g0 + u] : 0.0f;
    return v;
}

__global__ __launch_bounds__(NT) void stft_kernel(const float* __restrict__ x,
                                                  float* __restrict__ out)
{
    __shared__ float2 Abuf[2304];   // stage-in (padded)
    __shared__ float2 Bbuf[2304];   // working buffer (padded)

    const int t = threadIdx.x;
    const int pr = blockIdx.x;
    const int m0 = 2 * pr, m1 = m0 + 1;
    const int ba = m0 / FRAMES, fa = m0 - ba * FRAMES;
    const int bb = m1 / FRAMES, fb = m1 - bb * FRAMES;
    const float* xA = x + ba * SIG_LEN;
    const float* xB = x + bb * SIG_LEN;
    const int baseA = fa * STRIDE - PAD_L;
    const int baseB = fb * STRIDE - PAD_L;

    // ---- stage-in: Abuf[phys(n)] = hann(n) * (xA(n) + i*xB(n))
    // thread t owns n = 4t+u (chunk0) and n+1024 (chunk1), u = 0..3
    {
        const float CD = 0.999995293809576171875f;    // cos(2*pi/2048)
        const float SD = 3.0679567629659761e-3f;      // sin(2*pi/2048)
        float4 a0 = load4(xA, baseA + 4 * t);
        float4 a1 = load4(xA, baseA + 4 * t + 1024);
        float4 b0 = load4(xB, baseB + 4 * t);
        float4 b1 = load4(xB, baseB + 4 * t + 1024);
        const float* pa0 = (const float*)&a0;
        const float* pa1 = (const float*)&a1;
        const float* pb0 = (const float*)&b0;
        const float* pb1 = (const float*)&b1;
        float cs, sn;
        __sincosf(3.06796157577128245e-3f * (float)(4 * t), &sn, &cs);
        int p0 = phys(4 * t);           // 4t + (t>>1); contiguous for u=0..3
        #pragma unroll
        for (int u = 0; u < 4; u++) {
            float w0 = 0.5f - 0.5f * cs;   // hann(4t+u)
            float w1 = 0.5f + 0.5f * cs;   // hann(4t+u+1024)
            Abuf[p0 + u]        = make_float2(w0 * pa0[u], w0 * pb0[u]);
            Abuf[p0 + u + 1152] = make_float2(w1 * pa1[u], w1 * pb1[u]); // phys(+1024)=+1152
            float c2 = cs * CD - sn * SD;
            float s2 = sn * CD + cs * SD;
            cs = c2; sn = s2;
        }
    }
    __syncthreads();

    float2 E[8];

    // ---- pass 0: read bit-reversed from Abuf, radix-8 (T3=1), write Bbuf
    {
        const int rev3[8] = {0, 4, 2, 6, 1, 5, 3, 7};
        int rt = (int)(__brev((unsigned)t) >> 24);   // rev8(t)
        #pragma unroll
        for (int j = 0; j < 8; j++)
            E[j] = Abuf[phys((rev3[j] << 8) + rt)];

        const float R = 0.70710678118654752440f;
        bfly1(E[0], E[1]); bfly1(E[2], E[3]); bfly1(E[4], E[5]); bfly1(E[6], E[7]);
        bfly1(E[0], E[2]); bflyni(E[1], E[3]);
        bfly1(E[4], E[6]); bflyni(E[5], E[7]);
        bfly1(E[0], E[4]);
        {   // tw = (1-i)/sqrt2
            float2 h = E[5];
            float2 u = make_float2(R * (h.x + h.y), R * (h.y - h.x));
            E[5] = make_float2(E[1].x - u.x, E[1].y - u.y);
            E[1] = make_float2(E[1].x + u.x, E[1].y + u.y);
        }
        bflyni(E[2], E[6]);
        {   // tw = (-1-i)/sqrt2
            float2 h = E[7];
            float2 u = make_float2(R * (h.y - h.x), -R * (h.x + h.y));
            E[7] = make_float2(E[3].x - u.x, E[3].y - u.y);
            E[3] = make_float2(E[3].x + u.x, E[3].y + u.y);
        }
        int wb = 9 * t;   // phys(8t+j) contiguous
        #pragma unroll
        for (int j = 0; j < 8; j++) Bbuf[wb + j] = E[j];
    }
    __syncthreads();

    // ---- pass 1: h=8, T3 = W^(32*(t&7))
    {
        int bl = t & 7;
        int base = bl + ((t >> 3) << 6);
        #pragma unroll
        for (int j = 0; j < 8; j++) E[j] = Bbuf[phys(base + 8 * j)];
        float2 T3; __sincosf(-9.81747704246810387e-2f * (float)bl, &T3.y, &T3.x);
        pass_radix8(E, T3);
        #pragma unroll
        for (int j = 0; j < 8; j++) Bbuf[phys(base + 8 * j)] = E[j];
    }
    __syncthreads();

    // ---- pass 2: h=64, T3 = W^(4*(t&63))
    {
        int bl = t & 63;
        int base = bl + ((t >> 6) << 9);
        #pragma unroll
        for (int j = 0; j < 8; j++) E[j] = Bbuf[phys(base + 64 * j)];
        float2 T3; __sincosf(-1.22718463030851298e-2f * (float)bl, &T3.y, &T3.x);
        pass_radix8(E, T3);
        #pragma unroll
        for (int j = 0; j < 8; j++) Bbuf[phys(base + 64 * j)] = E[j];
    }
    __syncthreads();

    // ---- pass 3 + fused epilogue
    // groups c3a = t, c3b = 512-t (thread 0: 0 and 256); conjugate pairs
    // Z[f] <-> Z[2048-f] then live inside this thread's registers.
    {
        int c3a = t;
        int c3b = t ? (512 - t) : 256;
        float2 G[4], H[4];
        #pragma unroll
        for (int j = 0; j < 4; j++) G[j] = Bbuf[phys(c3a + 512 * j)];
        #pragma unroll
        for (int j = 0; j < 4; j++) H[j] = Bbuf[phys(c3b + 512 * j)];

        float2 T; __sincosf(-3.06796157577128245e-3f * (float)t, &T.y, &T.x); // W^t
        // W^(512-t) = -i * conj(W^t);  thread 0 needs W^256 = (1-i)/sqrt2
        const float R = 0.70710678118654752440f;
        float2 Tb = t ? make_float2(-T.y, -T.x) : make_float2(R, -R);

        pass_radix4(G, T);    // G[j] = Z[c3a + 512j]
        pass_radix4(H, Tb);   // H[j] = Z[c3b + 512j]

        int   bins[4];
        float2 zf[4], zg[4];
        zf[0] = G[0]; zf[1] = G[1]; zf[2] = H[0]; zf[3] = H[1];
        if (t) {
            bins[0] = t;        zg[0] = H[3];   // 2048-t
            bins[1] = t + 512;  zg[1] = H[2];   // 1536-t
            bins[2] = 512 - t;  zg[2] = G[3];   // 1536+t
            bins[3] = 1024 - t; zg[3] = G[2];   // 1024+t
        } else {
            bins[0] = 0;   zg[0] = G[0];
            bins[1] = 512; zg[1] = G[3];
            bins[2] = 256; zg[2] = H[3];
            bins[3] = 768; zg[3] = H[2];
        }

        float* outR = out;
        float* outI = out + (size_t)(BATCH * FRAMES) * FREQ;
        size_t oA = (size_t)m0 * FREQ;
        size_t oB = (size_t)m1 * FREQ;
        #pragma unroll
        for (int i = 0; i < 4; i++) {
            int f = bins[i];
            float2 Zf = zf[i], Zg = zg[i];
            outR[oA + f] = 0.5f * (Zf.x + Zg.x);
            outI[oA + f] = 0.5f * (Zf.y - Zg.y);
            outR[oB + f] = 0.5f * (Zf.y + Zg.y);
            outI[oB + f] = 0.5f * (Zg.x - Zf.x);
        }
    }
}

extern "C" void kernel_launch(void* const* d_in, const int* in_sizes, int n_in,
                              void* d_out, int out_size)
{
    const float* x = (const float*)d_in[0];   // input_signal [64, 32256, 1]
    float* out = (float*)d_out;               // [2, 4032, 1024]
    stft_kernel<<<NPAIRS, NT>>>(x, out);
}